// round 7
// baseline (speedup 1.0000x reference)
#include <cuda_runtime.h>
#include <cuda_fp16.h>
#include <cstdint>
#include <math.h>

// Qwen3.5 TopK Router — 3-pass FP16-split mma.sync(m16n8k16) + ldmatrix.
// KC=64 chunks (half the barriers, 2x latency-hiding window), 16 warps/CTA.
// x' = x*1024, w' = w*64; hi = f16_rn(v), lo = f16_rn(v-hi);
// acc += Ah*Bh + Ah*Bl + Al*Bh; logits = acc/65536. Residual ~2^-22.
//
// Output (float32): [T*E logits][T*K weights][T*K indices-as-float]

#define D_DIM  2048
#define E_EXP  128
#define TOPK   8
#define BM     128
#define KC     64                 // fp32 K per chunk
#define NCH    (D_DIM / KC)       // 32
#define NT     512
#define LPAD   129

#define SX      1024.0f
#define SW      64.0f
#define RESCALE (1.0f / 65536.0f)

// tile: 128 rows x 128B (64 halves) = 16 KB. Ah|Al|Bh|Bl per stage, 2 stages.
#define TILE_B   16384
#define STAGE_B  (4 * TILE_B)     // 65536
#define SMEM_B   131072

#define MMA_F16(d, a0, a1, a2, a3, b0, b1)                                    \
    asm volatile(                                                             \
        "mma.sync.aligned.m16n8k16.row.col.f32.f16.f16.f32 "                  \
        "{%0,%1,%2,%3}, {%4,%5,%6,%7}, {%8,%9}, {%0,%1,%2,%3};"               \
        : "+f"((d)[0]), "+f"((d)[1]), "+f"((d)[2]), "+f"((d)[3])              \
        : "r"(a0), "r"(a1), "r"(a2), "r"(a3), "r"(b0), "r"(b1))

#define LDSM_X4(r, addr)                                                      \
    asm volatile(                                                             \
        "ldmatrix.sync.aligned.m8n8.x4.shared.b16 {%0,%1,%2,%3}, [%4];"       \
        : "=r"((r)[0]), "=r"((r)[1]), "=r"((r)[2]), "=r"((r)[3])              \
        : "r"(addr))

static __device__ __forceinline__ uint32_t smem_u32(const void* p) {
    uint32_t a;
    asm("{ .reg .u64 t; cvta.to.shared.u64 t, %1; cvt.u32.u64 %0, t; }"
        : "=r"(a) : "l"(p));
    return a;
}
// split fp32 pair into packed hi/lo half2
static __device__ __forceinline__ void split2(float x0, float x1,
                                              uint32_t& hi, uint32_t& lo) {
    half2 h = __floats2half2_rn(x0, x1);
    float2 hf = __half22float2(h);
    half2 l = __floats2half2_rn(x0 - hf.x, x1 - hf.y);
    hi = *(uint32_t*)&h;
    lo = *(uint32_t*)&l;
}
// split a float4 (scaled) into hi/lo uint2 (4 halves each)
static __device__ __forceinline__ void split4(float4 v, float s,
                                              uint2& hi, uint2& lo) {
    uint32_t h0, l0, h1, l1;
    split2(v.x * s, v.y * s, h0, l0);
    split2(v.z * s, v.w * s, h1, l1);
    hi = make_uint2(h0, h1);
    lo = make_uint2(l0, l1);
}

__global__ __launch_bounds__(NT, 1)
void router_mma(const float* __restrict__ X,
                const float* __restrict__ W,
                float* __restrict__ out, int T)
{
    extern __shared__ __align__(16) uint32_t smem[];
    __shared__ float smax[BM];
    __shared__ float srsum[BM];

    const uint32_t sbase = smem_u32(smem);
    const int tid  = threadIdx.x;
    const int wid  = tid >> 5;
    const int lane = tid & 31;
    const int row0 = blockIdx.x * BM;

    // -------- producer mapping --------
    // warp w owns rows 8w..8w+7 of A and B. lane: row = 8w + (lane>>2);
    // q in 0..3: fp32 cols (lane&3)*4 + 16q .. +3 (coalesced float4 per q).
    const int prow = 8 * wid + (lane >> 2);
    const int l3   = lane & 3;
    const float* gA0 = X + (size_t)(row0 + prow) * D_DIM + l3 * 4;
    const float* gB0 = W + (size_t)prow * D_DIM + l3 * 4;
    // swizzled byte offset within a tile; soff(q) = soff0 ^ (q<<5)
    const uint32_t soff0 = (uint32_t)(prow * 128
                         + (((l3 >> 1) ^ (prow & 7)) << 4) + (l3 & 1) * 8);

    // -------- consumer mapping: warp grid 4(M) x 4(N), tile 32x32 --------
    const int g_  = lane >> 2;
    const int tg  = lane & 3;
    const int mrow0 = (wid & 3) * 32;
    const int ncol0 = (wid >> 2) * 32;

    // ldmatrix base offsets (tile-relative); addr = stage + (base ^ (kb<<5))
    uint32_t bAh[2], bAl[2], bBh[2], bBl[2];
    {
        const int rA  = (lane & 7) + ((lane >> 3) & 1) * 8;
        const int gsA = lane >> 4;                     // k8-half select
        #pragma unroll
        for (int mt = 0; mt < 2; mt++) {
            const int row = mrow0 + mt * 16 + rA;
            const uint32_t o = (uint32_t)(row * 128
                             + ((gsA ^ (row & 7)) << 4));
            bAh[mt] = o;
            bAl[mt] = o + TILE_B;
        }
        const int rB  = (lane & 7) + ((lane >> 4) << 3);
        const int gsB = (lane >> 3) & 1;
        #pragma unroll
        for (int p = 0; p < 2; p++) {
            const int row = ncol0 + p * 16 + rB;
            const uint32_t o = (uint32_t)(row * 128
                             + ((gsB ^ (row & 7)) << 4));
            bBh[p] = o + 2 * TILE_B;
            bBl[p] = o + 3 * TILE_B;
        }
    }

    float acc[2][4][4];
    #pragma unroll
    for (int mt = 0; mt < 2; mt++)
        #pragma unroll
        for (int nt = 0; nt < 4; nt++)
            #pragma unroll
            for (int i = 0; i < 4; i++) acc[mt][nt][i] = 0.0f;

    float4 ra[4], rb[4];

    // ---- prologue: chunk 0 -> stage 0 ----
    #pragma unroll
    for (int q = 0; q < 4; q++) {
        ra[q] = *(const float4*)(gA0 + q * 16);
        rb[q] = *(const float4*)(gB0 + q * 16);
    }
    {
        char* st = (char*)smem;
        #pragma unroll
        for (int q = 0; q < 4; q++) {
            const uint32_t so = soff0 ^ (q << 5);
            uint2 hi, lo;
            split4(ra[q], SX, hi, lo);
            *(uint2*)(st + so)              = hi;
            *(uint2*)(st + TILE_B + so)     = lo;
            split4(rb[q], SW, hi, lo);
            *(uint2*)(st + 2 * TILE_B + so) = hi;
            *(uint2*)(st + 3 * TILE_B + so) = lo;
        }
    }
    __syncthreads();

    // ---- main loop ----
    for (int c = 0; c < NCH; ++c) {
        if (c + 1 < NCH) {
            const int ko = (c + 1) * KC;
            #pragma unroll
            for (int q = 0; q < 4; q++) {
                ra[q] = *(const float4*)(gA0 + ko + q * 16);
                rb[q] = *(const float4*)(gB0 + ko + q * 16);
            }
        }

        const uint32_t stg = sbase + (uint32_t)(c & 1) * STAGE_B;

        #pragma unroll
        for (int kb = 0; kb < 4; kb++) {
            const uint32_t kx = (uint32_t)kb << 5;
            uint32_t ah[2][4], al[2][4], bh[2][4], bl[2][4];
            #pragma unroll
            for (int mt = 0; mt < 2; mt++) {
                LDSM_X4(ah[mt], stg + (bAh[mt] ^ kx));
                LDSM_X4(al[mt], stg + (bAl[mt] ^ kx));
            }
            #pragma unroll
            for (int p = 0; p < 2; p++) {
                LDSM_X4(bh[p], stg + (bBh[p] ^ kx));
                LDSM_X4(bl[p], stg + (bBl[p] ^ kx));
            }
            // nt -> (p = nt>>1, h = (nt&1)*2): b regs (h, h+1)
            #pragma unroll
            for (int mt = 0; mt < 2; mt++)
                #pragma unroll
                for (int nt = 0; nt < 4; nt++) {
                    const int p = nt >> 1, h = (nt & 1) * 2;
                    MMA_F16(acc[mt][nt], ah[mt][0], ah[mt][1], ah[mt][2], ah[mt][3],
                            bh[p][h], bh[p][h + 1]);
                }
            #pragma unroll
            for (int mt = 0; mt < 2; mt++)
                #pragma unroll
                for (int nt = 0; nt < 4; nt++) {
                    const int p = nt >> 1, h = (nt & 1) * 2;
                    MMA_F16(acc[mt][nt], ah[mt][0], ah[mt][1], ah[mt][2], ah[mt][3],
                            bl[p][h], bl[p][h + 1]);
                }
            #pragma unroll
            for (int mt = 0; mt < 2; mt++)
                #pragma unroll
                for (int nt = 0; nt < 4; nt++) {
                    const int p = nt >> 1, h = (nt & 1) * 2;
                    MMA_F16(acc[mt][nt], al[mt][0], al[mt][1], al[mt][2], al[mt][3],
                            bh[p][h], bh[p][h + 1]);
                }
        }

        if (c + 1 < NCH) {
            char* stn = (char*)smem + ((c + 1) & 1) * STAGE_B;
            #pragma unroll
            for (int q = 0; q < 4; q++) {
                const uint32_t so = soff0 ^ (q << 5);
                uint2 hi, lo;
                split4(ra[q], SX, hi, lo);
                *(uint2*)(stn + so)              = hi;
                *(uint2*)(stn + TILE_B + so)     = lo;
                split4(rb[q], SW, hi, lo);
                *(uint2*)(stn + 2 * TILE_B + so) = hi;
                *(uint2*)(stn + 3 * TILE_B + so) = lo;
            }
        }
        __syncthreads();
    }

    // ---- epilogue: rescale accum -> smem logits tile ----
    float* Ls = (float*)smem;   // [BM][LPAD]
    #pragma unroll
    for (int mt = 0; mt < 2; mt++) {
        #pragma unroll
        for (int nt = 0; nt < 4; nt++) {
            const int r_ = mrow0 + mt * 16 + g_;
            const int c_ = ncol0 + nt * 8 + tg * 2;
            Ls[r_ * LPAD + c_]           = acc[mt][nt][0] * RESCALE;
            Ls[r_ * LPAD + c_ + 1]       = acc[mt][nt][1] * RESCALE;
            Ls[(r_ + 8) * LPAD + c_]     = acc[mt][nt][2] * RESCALE;
            Ls[(r_ + 8) * LPAD + c_ + 1] = acc[mt][nt][3] * RESCALE;
        }
    }
    __syncthreads();

    // per-token max & exp-sum
    if (tid < BM) {
        const float* r = Ls + tid * LPAD;
        float m = r[0];
        #pragma unroll 4
        for (int e = 1; e < E_EXP; e++) m = fmaxf(m, r[e]);
        float s = 0.0f;
        #pragma unroll 4
        for (int e = 0; e < E_EXP; e++) s += __expf(r[e] - m);
        smax[tid]  = m;
        srsum[tid] = 1.0f / s;
    }
    __syncthreads();

    // softmax probs -> smem overwrite + coalesced logits write
    for (int i = tid; i < BM * E_EXP; i += NT) {
        const int t = i >> 7;
        const int e = i & 127;
        const float p = __expf(Ls[t * LPAD + e] - smax[t]) * srsum[t];
        Ls[t * LPAD + e] = p;
        out[(size_t)(row0 + t) * E_EXP + e] = p;
    }
    __syncthreads();

    // top-8 (strict > keeps lowest index on ties) + renormalize
    if (tid < BM) {
        float* r = Ls + tid * LPAD;
        float vals[TOPK];
        int   idxs[TOPK];
        float s = 0.0f;
        #pragma unroll
        for (int k = 0; k < TOPK; k++) {
            float bv = -1.0f;
            int   bi = 0;
            for (int e = 0; e < E_EXP; e++) {
                float v = r[e];
                if (v > bv) { bv = v; bi = e; }
            }
            r[bi]   = -1.0f;
            vals[k] = bv;
            idxs[k] = bi;
            s += bv;
        }
        const float rs = 1.0f / s;
        const size_t bw = (size_t)T * E_EXP + (size_t)(row0 + tid) * TOPK;
        const size_t bx = (size_t)T * E_EXP + (size_t)T * TOPK + (size_t)(row0 + tid) * TOPK;
        #pragma unroll
        for (int k = 0; k < TOPK; k++) {
            out[bw + k] = vals[k] * rs;
            out[bx + k] = (float)idxs[k];
        }
    }
}

extern "C" void kernel_launch(void* const* d_in, const int* in_sizes, int n_in,
                              void* d_out, int out_size)
{
    const float* X = (const float*)d_in[0];   // hidden_states [T, 2048]
    const float* W = (const float*)d_in[1];   // weight        [128, 2048]
    float* out = (float*)d_out;

    const int T = in_sizes[0] / D_DIM;        // 16384
    static int configured = -1;
    if (configured < 0) {
        cudaFuncSetAttribute(router_mma,
                             cudaFuncAttributeMaxDynamicSharedMemorySize, SMEM_B);
        configured = 1;
    }
    router_mma<<<T / BM, NT, SMEM_B>>>(X, W, out, T);
}

// round 8
// speedup vs baseline: 1.0067x; 1.0067x over previous
#include <cuda_runtime.h>
#include <cuda_fp16.h>
#include <cstdint>
#include <math.h>

// Qwen3.5 TopK Router — 3-pass FP16-split mma.sync(m16n8k16) + ldmatrix,
// 2 CTAs/SM (BM=64, 256 thr) to fill tensor-pipe bubbles across CTAs.
// x' = x*1024, w' = w*64; hi = f16_rn(v), lo = f16_rn(v-hi);
// acc += Ah*Bh + Ah*Bl + Al*Bh; logits = acc/65536. Residual ~2^-22.
//
// Output (float32): [T*E logits][T*K weights][T*K indices-as-float]

#define D_DIM  2048
#define E_EXP  128
#define TOPK   8
#define BM     64                 // tokens per CTA
#define KC     32                 // fp32 K per chunk
#define NCH    (D_DIM / KC)       // 64
#define NT     256
#define LPAD   129

#define SX      1024.0f
#define SW      64.0f
#define RESCALE (1.0f / 65536.0f)

// tiles (64B rows = 32 halves): Ah 64x64B=4K, Al 4K, Bh 128x64B=8K, Bl 8K
#define A_TILE_B 4096
#define B_TILE_B 8192
#define OFF_AH   0
#define OFF_AL   4096
#define OFF_BH   8192
#define OFF_BL   16384
#define STAGE_B  24576
#define SMEM_B   49152            // 2 stages; >= 64*129*4 epilogue

#define MMA_F16(d, a0, a1, a2, a3, b0, b1)                                    \
    asm volatile(                                                             \
        "mma.sync.aligned.m16n8k16.row.col.f32.f16.f16.f32 "                  \
        "{%0,%1,%2,%3}, {%4,%5,%6,%7}, {%8,%9}, {%0,%1,%2,%3};"               \
        : "+f"((d)[0]), "+f"((d)[1]), "+f"((d)[2]), "+f"((d)[3])              \
        : "r"(a0), "r"(a1), "r"(a2), "r"(a3), "r"(b0), "r"(b1))

#define LDSM_X4(r, addr)                                                      \
    asm volatile(                                                             \
        "ldmatrix.sync.aligned.m8n8.x4.shared.b16 {%0,%1,%2,%3}, [%4];"       \
        : "=r"((r)[0]), "=r"((r)[1]), "=r"((r)[2]), "=r"((r)[3])              \
        : "r"(addr))

static __device__ __forceinline__ uint32_t smem_u32(const void* p) {
    uint32_t a;
    asm("{ .reg .u64 t; cvta.to.shared.u64 t, %1; cvt.u32.u64 %0, t; }"
        : "=r"(a) : "l"(p));
    return a;
}
static __device__ __forceinline__ void split2(float x0, float x1,
                                              uint32_t& hi, uint32_t& lo) {
    half2 h = __floats2half2_rn(x0, x1);
    float2 hf = __half22float2(h);
    half2 l = __floats2half2_rn(x0 - hf.x, x1 - hf.y);
    hi = *(uint32_t*)&h;
    lo = *(uint32_t*)&l;
}
static __device__ __forceinline__ void split4(float4 v, float s,
                                              uint2& hi, uint2& lo) {
    uint32_t h0, l0, h1, l1;
    split2(v.x * s, v.y * s, h0, l0);
    split2(v.z * s, v.w * s, h1, l1);
    hi = make_uint2(h0, h1);
    lo = make_uint2(l0, l1);
}

__global__ __launch_bounds__(NT, 2)
void router_mma(const float* __restrict__ X,
                const float* __restrict__ W,
                float* __restrict__ out, int T)
{
    extern __shared__ __align__(16) uint32_t smem[];
    __shared__ float smax[BM];
    __shared__ float srsum[BM];

    const uint32_t sbase = smem_u32(smem);
    const int tid  = threadIdx.x;
    const int wid  = tid >> 5;
    const int lane = tid & 31;
    const int row0 = blockIdx.x * BM;

    // -------- producer mapping --------
    // 64B-row swizzle: byte = r*64 + ((g ^ ((r>>1)&3))<<4) + (lane&1)*8,
    // g = (lane&7)>>1. A: warp w rows 8w+4q+(lane>>3), q=0..1 (64 rows).
    // B: warp w rows 16w+4q+(lane>>3), q=0..3 (128 rows).
    const int psub = lane >> 3;
    const int pcol = (lane & 7) * 4;           // fp32 col 0..28
    const int pg   = (lane & 7) >> 1;          // 16B granule
    const int psb  = (lane & 1) * 8;           // byte offset in granule
    const float* gA[2];
    uint32_t soffA[2];
    #pragma unroll
    for (int q = 0; q < 2; q++) {
        const int r = 8 * wid + 4 * q + psub;
        gA[q] = X + (size_t)(row0 + r) * D_DIM + pcol;
        soffA[q] = (uint32_t)(r * 64 + ((pg ^ ((r >> 1) & 3)) << 4) + psb);
    }
    const float* gB[4];
    uint32_t soffB[4];
    #pragma unroll
    for (int q = 0; q < 4; q++) {
        const int r = 16 * wid + 4 * q + psub;
        gB[q] = W + (size_t)r * D_DIM + pcol;
        soffB[q] = (uint32_t)(r * 64 + ((pg ^ ((r >> 1) & 3)) << 4) + psb);
    }

    // -------- consumer mapping: warp grid 2(M) x 4(N), tile 32x32 --------
    const int g_  = lane >> 2;
    const int tg  = lane & 3;
    const int mrow0 = (wid & 1) * 32;
    const int ncol0 = (wid >> 1) * 32;

    uint32_t offA[2][2], offB[2][2];           // [mt|p][kb] tile-relative bytes
    {
        const int rA  = (lane & 7) + ((lane >> 3) & 1) * 8;
        const int gsA = lane >> 4;
        #pragma unroll
        for (int mt = 0; mt < 2; mt++) {
            const int row = mrow0 + mt * 16 + rA;
            const int sw  = (row >> 1) & 3;
            #pragma unroll
            for (int kb = 0; kb < 2; kb++)
                offA[mt][kb] = (uint32_t)(row * 64 + (((kb * 2 + gsA) ^ sw) << 4));
        }
        const int rB  = (lane & 7) + ((lane >> 4) << 3);
        const int gsB = (lane >> 3) & 1;
        #pragma unroll
        for (int p = 0; p < 2; p++) {
            const int row = ncol0 + p * 16 + rB;
            const int sw  = (row >> 1) & 3;
            #pragma unroll
            for (int kb = 0; kb < 2; kb++)
                offB[p][kb] = (uint32_t)(row * 64 + (((kb * 2 + gsB) ^ sw) << 4));
        }
    }

    float acc[2][4][4];
    #pragma unroll
    for (int mt = 0; mt < 2; mt++)
        #pragma unroll
        for (int nt = 0; nt < 4; nt++)
            #pragma unroll
            for (int i = 0; i < 4; i++) acc[mt][nt][i] = 0.0f;

    float4 ra[2], rb[4];

    // ---- prologue: chunk 0 -> stage 0 ----
    #pragma unroll
    for (int q = 0; q < 2; q++) ra[q] = *(const float4*)gA[q];
    #pragma unroll
    for (int q = 0; q < 4; q++) rb[q] = *(const float4*)gB[q];
    {
        char* st = (char*)smem;
        #pragma unroll
        for (int q = 0; q < 2; q++) {
            uint2 hi, lo;
            split4(ra[q], SX, hi, lo);
            *(uint2*)(st + OFF_AH + soffA[q]) = hi;
            *(uint2*)(st + OFF_AL + soffA[q]) = lo;
        }
        #pragma unroll
        for (int q = 0; q < 4; q++) {
            uint2 hi, lo;
            split4(rb[q], SW, hi, lo);
            *(uint2*)(st + OFF_BH + soffB[q]) = hi;
            *(uint2*)(st + OFF_BL + soffB[q]) = lo;
        }
    }
    __syncthreads();

    // ---- main loop ----
    for (int c = 0; c < NCH; ++c) {
        if (c + 1 < NCH) {
            const int ko = (c + 1) * KC;
            #pragma unroll
            for (int q = 0; q < 2; q++) ra[q] = *(const float4*)(gA[q] + ko);
            #pragma unroll
            for (int q = 0; q < 4; q++) rb[q] = *(const float4*)(gB[q] + ko);
        }

        const uint32_t stg = sbase + (uint32_t)(c & 1) * STAGE_B;

        #pragma unroll
        for (int kb = 0; kb < 2; kb++) {
            uint32_t ah[2][4], al[2][4], bh[2][4], bl[2][4];
            #pragma unroll
            for (int mt = 0; mt < 2; mt++) {
                LDSM_X4(ah[mt], stg + OFF_AH + offA[mt][kb]);
                LDSM_X4(al[mt], stg + OFF_AL + offA[mt][kb]);
            }
            #pragma unroll
            for (int p = 0; p < 2; p++) {
                LDSM_X4(bh[p], stg + OFF_BH + offB[p][kb]);
                LDSM_X4(bl[p], stg + OFF_BL + offB[p][kb]);
            }
            #pragma unroll
            for (int mt = 0; mt < 2; mt++)
                #pragma unroll
                for (int nt = 0; nt < 4; nt++) {
                    const int p = nt >> 1, h = (nt & 1) * 2;
                    MMA_F16(acc[mt][nt], ah[mt][0], ah[mt][1], ah[mt][2], ah[mt][3],
                            bh[p][h], bh[p][h + 1]);
                }
            #pragma unroll
            for (int mt = 0; mt < 2; mt++)
                #pragma unroll
                for (int nt = 0; nt < 4; nt++) {
                    const int p = nt >> 1, h = (nt & 1) * 2;
                    MMA_F16(acc[mt][nt], ah[mt][0], ah[mt][1], ah[mt][2], ah[mt][3],
                            bl[p][h], bl[p][h + 1]);
                }
            #pragma unroll
            for (int mt = 0; mt < 2; mt++)
                #pragma unroll
                for (int nt = 0; nt < 4; nt++) {
                    const int p = nt >> 1, h = (nt & 1) * 2;
                    MMA_F16(acc[mt][nt], al[mt][0], al[mt][1], al[mt][2], al[mt][3],
                            bh[p][h], bh[p][h + 1]);
                }
        }

        if (c + 1 < NCH) {
            char* stn = (char*)smem + ((c + 1) & 1) * STAGE_B;
            #pragma unroll
            for (int q = 0; q < 2; q++) {
                uint2 hi, lo;
                split4(ra[q], SX, hi, lo);
                *(uint2*)(stn + OFF_AH + soffA[q]) = hi;
                *(uint2*)(stn + OFF_AL + soffA[q]) = lo;
            }
            #pragma unroll
            for (int q = 0; q < 4; q++) {
                uint2 hi, lo;
                split4(rb[q], SW, hi, lo);
                *(uint2*)(stn + OFF_BH + soffB[q]) = hi;
                *(uint2*)(stn + OFF_BL + soffB[q]) = lo;
            }
        }
        __syncthreads();
    }

    // ---- epilogue: rescale accum -> smem logits tile ----
    float* Ls = (float*)smem;   // [BM][LPAD] = 33024 B
    #pragma unroll
    for (int mt = 0; mt < 2; mt++) {
        #pragma unroll
        for (int nt = 0; nt < 4; nt++) {
            const int r_ = mrow0 + mt * 16 + g_;
            const int c_ = ncol0 + nt * 8 + tg * 2;
            Ls[r_ * LPAD + c_]           = acc[mt][nt][0] * RESCALE;
            Ls[r_ * LPAD + c_ + 1]       = acc[mt][nt][1] * RESCALE;
            Ls[(r_ + 8) * LPAD + c_]     = acc[mt][nt][2] * RESCALE;
            Ls[(r_ + 8) * LPAD + c_ + 1] = acc[mt][nt][3] * RESCALE;
        }
    }
    __syncthreads();

    // per-token max & exp-sum
    if (tid < BM) {
        const float* r = Ls + tid * LPAD;
        float m = r[0];
        #pragma unroll 4
        for (int e = 1; e < E_EXP; e++) m = fmaxf(m, r[e]);
        float s = 0.0f;
        #pragma unroll 4
        for (int e = 0; e < E_EXP; e++) s += __expf(r[e] - m);
        smax[tid]  = m;
        srsum[tid] = 1.0f / s;
    }
    __syncthreads();

    // softmax probs -> smem overwrite + coalesced logits write
    for (int i = tid; i < BM * E_EXP; i += NT) {
        const int t = i >> 7;
        const int e = i & 127;
        const float p = __expf(Ls[t * LPAD + e] - smax[t]) * srsum[t];
        Ls[t * LPAD + e] = p;
        out[(size_t)(row0 + t) * E_EXP + e] = p;
    }
    __syncthreads();

    // top-8 (strict > keeps lowest index on ties) + renormalize
    if (tid < BM) {
        float* r = Ls + tid * LPAD;
        float vals[TOPK];
        int   idxs[TOPK];
        float s = 0.0f;
        #pragma unroll
        for (int k = 0; k < TOPK; k++) {
            float bv = -1.0f;
            int   bi = 0;
            for (int e = 0; e < E_EXP; e++) {
                float v = r[e];
                if (v > bv) { bv = v; bi = e; }
            }
            r[bi]   = -1.0f;
            vals[k] = bv;
            idxs[k] = bi;
            s += bv;
        }
        const float rs = 1.0f / s;
        const size_t bw = (size_t)T * E_EXP + (size_t)(row0 + tid) * TOPK;
        const size_t bx = (size_t)T * E_EXP + (size_t)T * TOPK + (size_t)(row0 + tid) * TOPK;
        #pragma unroll
        for (int k = 0; k < TOPK; k++) {
            out[bw + k] = vals[k] * rs;
            out[bx + k] = (float)idxs[k];
        }
    }
}

extern "C" void kernel_launch(void* const* d_in, const int* in_sizes, int n_in,
                              void* d_out, int out_size)
{
    const float* X = (const float*)d_in[0];   // hidden_states [T, 2048]
    const float* W = (const float*)d_in[1];   // weight        [128, 2048]
    float* out = (float*)d_out;

    const int T = in_sizes[0] / D_DIM;        // 16384
    static int configured = -1;
    if (configured < 0) {
        cudaFuncSetAttribute(router_mma,
                             cudaFuncAttributeMaxDynamicSharedMemorySize, SMEM_B);
        configured = 1;
    }
    router_mma<<<T / BM, NT, SMEM_B>>>(X, W, out, T);
}

// round 9
// speedup vs baseline: 1.0283x; 1.0215x over previous
#include <cuda_runtime.h>
#include <cuda_fp16.h>
#include <cstdint>
#include <math.h>

// Qwen3.5 TopK Router — 3-pass FP16-split mma.sync(m16n8k16) + ldmatrix.
// W (1MB) is pre-split into swizzled fp16 hi/lo tiles by a tiny pre-kernel;
// mainloop streams B via cp.async (no B producer work). A path as round 6.
// x' = x*1024, w' = w*64; hi = f16_rn(v), lo = f16_rn(v-hi);
// acc += Ah*Bh + Ah*Bl + Al*Bh; logits = acc/65536. Residual ~2^-22.
//
// Output (float32): [T*E logits][T*K weights][T*K indices-as-float]

#define D_DIM  2048
#define E_EXP  128
#define TOPK   8
#define BM     128
#define KC     32                 // fp32 K per chunk
#define NCH    (D_DIM / KC)       // 64
#define NT     512
#define LPAD   129

#define SX      1024.0f
#define SW      64.0f
#define RESCALE (1.0f / 65536.0f)

// stage layout (64B rows, granule swizzle g ^ ((r>>1)&3)):
//   Ah 8KB | Al 8KB | Bh 8KB | Bl 8KB
#define OFF_AH   0
#define OFF_AL   8192
#define OFF_BH   16384
#define OFF_BL   24576
#define STAGE_B  32768
#define SMEM_B   66560            // 2 stages (64K) / epilogue 128*129*4 alias

// pre-split W: [chunk 0..63][hi 8KB | lo 8KB]
__device__ __align__(16) unsigned char g_wbuf[NCH * 16384];

#define MMA_F16(d, a0, a1, a2, a3, b0, b1)                                    \
    asm volatile(                                                             \
        "mma.sync.aligned.m16n8k16.row.col.f32.f16.f16.f32 "                  \
        "{%0,%1,%2,%3}, {%4,%5,%6,%7}, {%8,%9}, {%0,%1,%2,%3};"               \
        : "+f"((d)[0]), "+f"((d)[1]), "+f"((d)[2]), "+f"((d)[3])              \
        : "r"(a0), "r"(a1), "r"(a2), "r"(a3), "r"(b0), "r"(b1))

#define LDSM_X4(r, addr)                                                      \
    asm volatile(                                                             \
        "ldmatrix.sync.aligned.m8n8.x4.shared.b16 {%0,%1,%2,%3}, [%4];"       \
        : "=r"((r)[0]), "=r"((r)[1]), "=r"((r)[2]), "=r"((r)[3])              \
        : "r"(addr))

static __device__ __forceinline__ uint32_t smem_u32(const void* p) {
    uint32_t a;
    asm("{ .reg .u64 t; cvta.to.shared.u64 t, %1; cvt.u32.u64 %0, t; }"
        : "=r"(a) : "l"(p));
    return a;
}
static __device__ __forceinline__ void split2(float x0, float x1,
                                              uint32_t& hi, uint32_t& lo) {
    half2 h = __floats2half2_rn(x0, x1);
    float2 hf = __half22float2(h);
    half2 l = __floats2half2_rn(x0 - hf.x, x1 - hf.y);
    hi = *(uint32_t*)&h;
    lo = *(uint32_t*)&l;
}
static __device__ __forceinline__ void split4(float4 v, float s,
                                              uint2& hi, uint2& lo) {
    uint32_t h0, l0, h1, l1;
    split2(v.x * s, v.y * s, h0, l0);
    split2(v.z * s, v.w * s, h1, l1);
    hi = make_uint2(h0, h1);
    lo = make_uint2(l0, l1);
}
static __device__ __forceinline__ void cpasync16(uint32_t dst, const void* src) {
    asm volatile("cp.async.cg.shared.global [%0], [%1], 16;"
                 :: "r"(dst), "l"(src) : "memory");
}
static __device__ __forceinline__ void cp_commit() {
    asm volatile("cp.async.commit_group;" ::: "memory");
}
static __device__ __forceinline__ void cp_wait0() {
    asm volatile("cp.async.wait_group 0;" ::: "memory");
}

// ---------------- pre-kernel: split W into swizzled hi/lo tiles ----------
__global__ void prep_w(const float* __restrict__ W)
{
    const int t = blockIdx.x * blockDim.x + threadIdx.x;   // 0..32767
    const int g = t & 3;              // 16B granule (8 k-values)
    const int r = (t >> 2) & 127;     // expert row
    const int c = t >> 9;             // chunk
    const float* src = W + (size_t)r * D_DIM + c * KC + g * 8;

    uint32_t hi[4], lo[4];
    #pragma unroll
    for (int i = 0; i < 4; i++)
        split2(src[2 * i] * SW, src[2 * i + 1] * SW, hi[i], lo[i]);

    const uint32_t pos = (uint32_t)(r * 64 + ((g ^ ((r >> 1) & 3)) << 4));
    *(uint4*)(g_wbuf + (size_t)c * 16384 + pos) =
        make_uint4(hi[0], hi[1], hi[2], hi[3]);
    *(uint4*)(g_wbuf + (size_t)c * 16384 + 8192 + pos) =
        make_uint4(lo[0], lo[1], lo[2], lo[3]);
}

// ---------------- main kernel ----------------
__global__ __launch_bounds__(NT, 1)
void router_mma(const float* __restrict__ X,
                float* __restrict__ out, int T)
{
    extern __shared__ __align__(16) uint32_t smem[];
    __shared__ float smax[BM];
    __shared__ float srsum[BM];

    const uint32_t sbase = smem_u32(smem);
    const int tid  = threadIdx.x;
    const int wid  = tid >> 5;
    const int lane = tid & 31;
    const int row0 = blockIdx.x * BM;

    // -------- A producer mapping (round 6) --------
    const int psub = lane >> 3;
    const int pcol = (lane & 7) * 4;
    const int pg   = (lane & 7) >> 1;
    const int psb  = (lane & 1) * 8;
    const float* gA[2];
    uint32_t soffA[2];
    #pragma unroll
    for (int q = 0; q < 2; q++) {
        const int r = 8 * wid + 4 * q + psub;
        gA[q] = X + (size_t)(row0 + r) * D_DIM + pcol;
        soffA[q] = (uint32_t)(r * 64 + ((pg ^ ((r >> 1) & 3)) << 4) + psb);
    }
    // B cp.async: thread tid copies granule tid of hi and lo tiles (linear)
    const uint32_t boff = (uint32_t)tid * 16;

    // -------- consumer mapping: warp grid 4(M) x 4(N), tile 32x32 --------
    const int g_  = lane >> 2;
    const int tg  = lane & 3;
    const int mrow0 = (wid & 3) * 32;
    const int ncol0 = (wid >> 2) * 32;

    uint32_t offA[2][2], offB[2][2];
    {
        const int rA  = (lane & 7) + ((lane >> 3) & 1) * 8;
        const int gsA = lane >> 4;
        #pragma unroll
        for (int mt = 0; mt < 2; mt++) {
            const int row = mrow0 + mt * 16 + rA;
            const int sw  = (row >> 1) & 3;
            #pragma unroll
            for (int kb = 0; kb < 2; kb++)
                offA[mt][kb] = (uint32_t)(row * 64 + (((kb * 2 + gsA) ^ sw) << 4));
        }
        const int rB  = (lane & 7) + ((lane >> 4) << 3);
        const int gsB = (lane >> 3) & 1;
        #pragma unroll
        for (int p = 0; p < 2; p++) {
            const int row = ncol0 + p * 16 + rB;
            const int sw  = (row >> 1) & 3;
            #pragma unroll
            for (int kb = 0; kb < 2; kb++)
                offB[p][kb] = (uint32_t)(row * 64 + (((kb * 2 + gsB) ^ sw) << 4));
        }
    }

    float acc[2][4][4];
    #pragma unroll
    for (int mt = 0; mt < 2; mt++)
        #pragma unroll
        for (int nt = 0; nt < 4; nt++)
            #pragma unroll
            for (int i = 0; i < 4; i++) acc[mt][nt][i] = 0.0f;

    float4 ra[2];

    // ---- prologue: chunk 0 -> stage 0 ----
    cpasync16(sbase + OFF_BH + boff, g_wbuf + boff);
    cpasync16(sbase + OFF_BL + boff, g_wbuf + 8192 + boff);
    cp_commit();
    #pragma unroll
    for (int q = 0; q < 2; q++) ra[q] = *(const float4*)gA[q];
    {
        char* st = (char*)smem;
        #pragma unroll
        for (int q = 0; q < 2; q++) {
            uint2 hi, lo;
            split4(ra[q], SX, hi, lo);
            *(uint2*)(st + OFF_AH + soffA[q]) = hi;
            *(uint2*)(st + OFF_AL + soffA[q]) = lo;
        }
    }
    cp_wait0();
    __syncthreads();

    // ---- main loop ----
    for (int c = 0; c < NCH; ++c) {
        // prefetch chunk c+1: A -> regs, B -> other stage via cp.async
        if (c + 1 < NCH) {
            const uint32_t stn = sbase + (uint32_t)((c + 1) & 1) * STAGE_B;
            const unsigned char* wsrc = g_wbuf + (size_t)(c + 1) * 16384;
            cpasync16(stn + OFF_BH + boff, wsrc + boff);
            cpasync16(stn + OFF_BL + boff, wsrc + 8192 + boff);
            const int ko = (c + 1) * KC;
            #pragma unroll
            for (int q = 0; q < 2; q++) ra[q] = *(const float4*)(gA[q] + ko);
        }
        cp_commit();

        const uint32_t stg = sbase + (uint32_t)(c & 1) * STAGE_B;

        #pragma unroll
        for (int kb = 0; kb < 2; kb++) {
            uint32_t ah[2][4], al[2][4], bh[2][4], bl[2][4];
            #pragma unroll
            for (int mt = 0; mt < 2; mt++) {
                LDSM_X4(ah[mt], stg + OFF_AH + offA[mt][kb]);
                LDSM_X4(al[mt], stg + OFF_AL + offA[mt][kb]);
            }
            #pragma unroll
            for (int p = 0; p < 2; p++) {
                LDSM_X4(bh[p], stg + OFF_BH + offB[p][kb]);
                LDSM_X4(bl[p], stg + OFF_BL + offB[p][kb]);
            }
            #pragma unroll
            for (int mt = 0; mt < 2; mt++)
                #pragma unroll
                for (int nt = 0; nt < 4; nt++) {
                    const int p = nt >> 1, h = (nt & 1) * 2;
                    MMA_F16(acc[mt][nt], ah[mt][0], ah[mt][1], ah[mt][2], ah[mt][3],
                            bh[p][h], bh[p][h + 1]);
                }
            #pragma unroll
            for (int mt = 0; mt < 2; mt++)
                #pragma unroll
                for (int nt = 0; nt < 4; nt++) {
                    const int p = nt >> 1, h = (nt & 1) * 2;
                    MMA_F16(acc[mt][nt], ah[mt][0], ah[mt][1], ah[mt][2], ah[mt][3],
                            bl[p][h], bl[p][h + 1]);
                }
            #pragma unroll
            for (int mt = 0; mt < 2; mt++)
                #pragma unroll
                for (int nt = 0; nt < 4; nt++) {
                    const int p = nt >> 1, h = (nt & 1) * 2;
                    MMA_F16(acc[mt][nt], al[mt][0], al[mt][1], al[mt][2], al[mt][3],
                            bh[p][h], bh[p][h + 1]);
                }
        }

        // commit A(c+1) to the other stage; wait B(c+1); barrier
        if (c + 1 < NCH) {
            char* stn = (char*)smem + ((c + 1) & 1) * STAGE_B;
            #pragma unroll
            for (int q = 0; q < 2; q++) {
                uint2 hi, lo;
                split4(ra[q], SX, hi, lo);
                *(uint2*)(stn + OFF_AH + soffA[q]) = hi;
                *(uint2*)(stn + OFF_AL + soffA[q]) = lo;
            }
        }
        cp_wait0();
        __syncthreads();
    }

    // ---- epilogue: rescale accum -> smem logits tile ----
    float* Ls = (float*)smem;   // [BM][LPAD]
    #pragma unroll
    for (int mt = 0; mt < 2; mt++) {
        #pragma unroll
        for (int nt = 0; nt < 4; nt++) {
            const int r_ = mrow0 + mt * 16 + g_;
            const int c_ = ncol0 + nt * 8 + tg * 2;
            Ls[r_ * LPAD + c_]           = acc[mt][nt][0] * RESCALE;
            Ls[r_ * LPAD + c_ + 1]       = acc[mt][nt][1] * RESCALE;
            Ls[(r_ + 8) * LPAD + c_]     = acc[mt][nt][2] * RESCALE;
            Ls[(r_ + 8) * LPAD + c_ + 1] = acc[mt][nt][3] * RESCALE;
        }
    }
    __syncthreads();

    // per-token max & exp-sum
    if (tid < BM) {
        const float* r = Ls + tid * LPAD;
        float m = r[0];
        #pragma unroll 4
        for (int e = 1; e < E_EXP; e++) m = fmaxf(m, r[e]);
        float s = 0.0f;
        #pragma unroll 4
        for (int e = 0; e < E_EXP; e++) s += __expf(r[e] - m);
        smax[tid]  = m;
        srsum[tid] = 1.0f / s;
    }
    __syncthreads();

    // softmax probs -> smem overwrite + coalesced logits write
    for (int i = tid; i < BM * E_EXP; i += NT) {
        const int t = i >> 7;
        const int e = i & 127;
        const float p = __expf(Ls[t * LPAD + e] - smax[t]) * srsum[t];
        Ls[t * LPAD + e] = p;
        out[(size_t)(row0 + t) * E_EXP + e] = p;
    }
    __syncthreads();

    // top-8 (strict > keeps lowest index on ties) + renormalize
    if (tid < BM) {
        float* r = Ls + tid * LPAD;
        float vals[TOPK];
        int   idxs[TOPK];
        float s = 0.0f;
        #pragma unroll
        for (int k = 0; k < TOPK; k++) {
            float bv = -1.0f;
            int   bi = 0;
            for (int e = 0; e < E_EXP; e++) {
                float v = r[e];
                if (v > bv) { bv = v; bi = e; }
            }
            r[bi]   = -1.0f;
            vals[k] = bv;
            idxs[k] = bi;
            s += bv;
        }
        const float rs = 1.0f / s;
        const size_t bw = (size_t)T * E_EXP + (size_t)(row0 + tid) * TOPK;
        const size_t bx = (size_t)T * E_EXP + (size_t)T * TOPK + (size_t)(row0 + tid) * TOPK;
        #pragma unroll
        for (int k = 0; k < TOPK; k++) {
            out[bw + k] = vals[k] * rs;
            out[bx + k] = (float)idxs[k];
        }
    }
}

extern "C" void kernel_launch(void* const* d_in, const int* in_sizes, int n_in,
                              void* d_out, int out_size)
{
    const float* X = (const float*)d_in[0];   // hidden_states [T, 2048]
    const float* W = (const float*)d_in[1];   // weight        [128, 2048]
    float* out = (float*)d_out;

    const int T = in_sizes[0] / D_DIM;        // 16384
    static int configured = -1;
    if (configured < 0) {
        cudaFuncSetAttribute(router_mma,
                             cudaFuncAttributeMaxDynamicSharedMemorySize, SMEM_B);
        configured = 1;
    }
    prep_w<<<128, 256>>>(W);                  // 1 MB split, ~2 us
    router_mma<<<T / BM, NT, SMEM_B>>>(X, out, T);
}

// round 10
// speedup vs baseline: 1.0679x; 1.0385x over previous
#include <cuda_runtime.h>
#include <cuda_fp16.h>
#include <cstdint>
#include <math.h>

// Qwen3.5 TopK Router — 3-pass FP16-split mma.sync(m16n8k16) + ldmatrix,
// phase-staggered: warp-parity kb order + JIT pass-ordered fragment loads
// so smem (LDSM) and tensor (HMMA) phases overlap across warps instead of
// alternating in lockstep behind the per-chunk barrier.
// x' = x*1024, w' = w*64; hi = f16_rn(v), lo = f16_rn(v-hi);
// acc += Ah*Bh (+ Al*Bh + Ah*Bl); logits = acc/65536. Residual ~2^-22.
//
// Output (float32): [T*E logits][T*K weights][T*K indices-as-float]

#define D_DIM  2048
#define E_EXP  128
#define TOPK   8
#define BM     128
#define KC     32                 // fp32 K per chunk
#define NCH    (D_DIM / KC)       // 64
#define NT     512
#define LPAD   129

#define SX      1024.0f
#define SW      64.0f
#define RESCALE (1.0f / 65536.0f)

// stage: Ah 8K | Al 8K | Bh 8K | Bl 8K (64B rows, granule swizzle)
#define OFF_AH   0
#define OFF_AL   8192
#define OFF_BH   16384
#define OFF_BL   24576
#define STAGE_B  32768
#define SMEM_B   66560            // 2 stages / 128*129*4 epilogue alias

#define MMA_F16(d, a0, a1, a2, a3, b0, b1)                                    \
    asm volatile(                                                             \
        "mma.sync.aligned.m16n8k16.row.col.f32.f16.f16.f32 "                  \
        "{%0,%1,%2,%3}, {%4,%5,%6,%7}, {%8,%9}, {%0,%1,%2,%3};"               \
        : "+f"((d)[0]), "+f"((d)[1]), "+f"((d)[2]), "+f"((d)[3])              \
        : "r"(a0), "r"(a1), "r"(a2), "r"(a3), "r"(b0), "r"(b1))

#define LDSM_X4(r, addr)                                                      \
    asm volatile(                                                             \
        "ldmatrix.sync.aligned.m8n8.x4.shared.b16 {%0,%1,%2,%3}, [%4];"       \
        : "=r"((r)[0]), "=r"((r)[1]), "=r"((r)[2]), "=r"((r)[3])              \
        : "r"(addr))

static __device__ __forceinline__ uint32_t smem_u32(const void* p) {
    uint32_t a;
    asm("{ .reg .u64 t; cvta.to.shared.u64 t, %1; cvt.u32.u64 %0, t; }"
        : "=r"(a) : "l"(p));
    return a;
}
static __device__ __forceinline__ void split2(float x0, float x1,
                                              uint32_t& hi, uint32_t& lo) {
    half2 h = __floats2half2_rn(x0, x1);
    float2 hf = __half22float2(h);
    half2 l = __floats2half2_rn(x0 - hf.x, x1 - hf.y);
    hi = *(uint32_t*)&h;
    lo = *(uint32_t*)&l;
}
static __device__ __forceinline__ void split4(float4 v, float s,
                                              uint2& hi, uint2& lo) {
    uint32_t h0, l0, h1, l1;
    split2(v.x * s, v.y * s, h0, l0);
    split2(v.z * s, v.w * s, h1, l1);
    hi = make_uint2(h0, h1);
    lo = make_uint2(l0, l1);
}

__global__ __launch_bounds__(NT, 1)
void router_mma(const float* __restrict__ X,
                const float* __restrict__ W,
                float* __restrict__ out, int T)
{
    extern __shared__ __align__(16) uint32_t smem[];
    __shared__ float smax[BM];
    __shared__ float srsum[BM];

    const uint32_t sbase = smem_u32(smem);
    const int tid  = threadIdx.x;
    const int wid  = tid >> 5;
    const int lane = tid & 31;
    const int row0 = blockIdx.x * BM;

    // -------- producer mapping (64B rows, swizzle g ^ ((r>>1)&3)) --------
    const int psub = lane >> 3;
    const int pcol = (lane & 7) * 4;
    const int pg   = (lane & 7) >> 1;
    const int psb  = (lane & 1) * 8;
    const float* gA[2];
    const float* gB[2];
    uint32_t soff[2];
    #pragma unroll
    for (int q = 0; q < 2; q++) {
        const int r = 8 * wid + 4 * q + psub;
        gA[q] = X + (size_t)(row0 + r) * D_DIM + pcol;
        gB[q] = W + (size_t)r * D_DIM + pcol;
        soff[q] = (uint32_t)(r * 64 + ((pg ^ ((r >> 1) & 3)) << 4) + psb);
    }

    // -------- consumer mapping: warp grid 4(M) x 4(N), tile 32x32 --------
    const int g_  = lane >> 2;
    const int tg  = lane & 3;
    const int mrow0 = (wid & 3) * 32;
    const int ncol0 = (wid >> 2) * 32;
    const int kbo   = wid & 1;          // warp-parity kb stagger

    uint32_t offA[2][2], offB[2][2];
    {
        const int rA  = (lane & 7) + ((lane >> 3) & 1) * 8;
        const int gsA = lane >> 4;
        #pragma unroll
        for (int mt = 0; mt < 2; mt++) {
            const int row = mrow0 + mt * 16 + rA;
            const int sw  = (row >> 1) & 3;
            #pragma unroll
            for (int kb = 0; kb < 2; kb++)
                offA[mt][kb] = (uint32_t)(row * 64 + (((kb * 2 + gsA) ^ sw) << 4));
        }
        const int rB  = (lane & 7) + ((lane >> 4) << 3);
        const int gsB = (lane >> 3) & 1;
        #pragma unroll
        for (int p = 0; p < 2; p++) {
            const int row = ncol0 + p * 16 + rB;
            const int sw  = (row >> 1) & 3;
            #pragma unroll
            for (int kb = 0; kb < 2; kb++)
                offB[p][kb] = (uint32_t)(row * 64 + (((kb * 2 + gsB) ^ sw) << 4));
        }
    }

    float acc[2][4][4];
    #pragma unroll
    for (int mt = 0; mt < 2; mt++)
        #pragma unroll
        for (int nt = 0; nt < 4; nt++)
            #pragma unroll
            for (int i = 0; i < 4; i++) acc[mt][nt][i] = 0.0f;

    float4 ra[2], rb[2];

    // ---- prologue: chunk 0 -> stage 0 ----
    #pragma unroll
    for (int q = 0; q < 2; q++) {
        ra[q] = *(const float4*)gA[q];
        rb[q] = *(const float4*)gB[q];
    }
    {
        char* st = (char*)smem;
        #pragma unroll
        for (int q = 0; q < 2; q++) {
            uint2 hi, lo;
            split4(ra[q], SX, hi, lo);
            *(uint2*)(st + OFF_AH + soff[q]) = hi;
            *(uint2*)(st + OFF_AL + soff[q]) = lo;
            split4(rb[q], SW, hi, lo);
            *(uint2*)(st + OFF_BH + soff[q]) = hi;
            *(uint2*)(st + OFF_BL + soff[q]) = lo;
        }
    }
    __syncthreads();

    // ---- main loop ----
    for (int c = 0; c < NCH; ++c) {
        if (c + 1 < NCH) {
            const int ko = (c + 1) * KC;
            #pragma unroll
            for (int q = 0; q < 2; q++) {
                ra[q] = *(const float4*)(gA[q] + ko);
                rb[q] = *(const float4*)(gB[q] + ko);
            }
        }

        const uint32_t stg = sbase + (uint32_t)(c & 1) * STAGE_B;

        #pragma unroll
        for (int kbi = 0; kbi < 2; kbi++) {
            const int kb = kbi ^ kbo;       // stagger phase across warps
            uint32_t ah[2][4], al[2][4], bh[2][4], bl[2][4];

            // JIT loads: (ah,bh) -> hh; al -> lh; bl -> hl
            #pragma unroll
            for (int mt = 0; mt < 2; mt++)
                LDSM_X4(ah[mt], stg + OFF_AH + offA[mt][kb]);
            #pragma unroll
            for (int p = 0; p < 2; p++)
                LDSM_X4(bh[p], stg + OFF_BH + offB[p][kb]);

            #pragma unroll
            for (int mt = 0; mt < 2; mt++)
                #pragma unroll
                for (int nt = 0; nt < 4; nt++) {
                    const int p = nt >> 1, h = (nt & 1) * 2;
                    MMA_F16(acc[mt][nt], ah[mt][0], ah[mt][1], ah[mt][2], ah[mt][3],
                            bh[p][h], bh[p][h + 1]);
                }

            #pragma unroll
            for (int mt = 0; mt < 2; mt++)
                LDSM_X4(al[mt], stg + OFF_AL + offA[mt][kb]);

            #pragma unroll
            for (int mt = 0; mt < 2; mt++)
                #pragma unroll
                for (int nt = 0; nt < 4; nt++) {
                    const int p = nt >> 1, h = (nt & 1) * 2;
                    MMA_F16(acc[mt][nt], al[mt][0], al[mt][1], al[mt][2], al[mt][3],
                            bh[p][h], bh[p][h + 1]);
                }

            #pragma unroll
            for (int p = 0; p < 2; p++)
                LDSM_X4(bl[p], stg + OFF_BL + offB[p][kb]);

            #pragma unroll
            for (int mt = 0; mt < 2; mt++)
                #pragma unroll
                for (int nt = 0; nt < 4; nt++) {
                    const int p = nt >> 1, h = (nt & 1) * 2;
                    MMA_F16(acc[mt][nt], ah[mt][0], ah[mt][1], ah[mt][2], ah[mt][3],
                            bl[p][h], bl[p][h + 1]);
                }
        }

        if (c + 1 < NCH) {
            char* stn = (char*)smem + ((c + 1) & 1) * STAGE_B;
            #pragma unroll
            for (int q = 0; q < 2; q++) {
                uint2 hi, lo;
                split4(ra[q], SX, hi, lo);
                *(uint2*)(stn + OFF_AH + soff[q]) = hi;
                *(uint2*)(stn + OFF_AL + soff[q]) = lo;
                split4(rb[q], SW, hi, lo);
                *(uint2*)(stn + OFF_BH + soff[q]) = hi;
                *(uint2*)(stn + OFF_BL + soff[q]) = lo;
            }
        }
        __syncthreads();
    }

    // ---- epilogue: rescale accum -> smem logits tile ----
    float* Ls = (float*)smem;   // [BM][LPAD]
    #pragma unroll
    for (int mt = 0; mt < 2; mt++) {
        #pragma unroll
        for (int nt = 0; nt < 4; nt++) {
            const int r_ = mrow0 + mt * 16 + g_;
            const int c_ = ncol0 + nt * 8 + tg * 2;
            Ls[r_ * LPAD + c_]           = acc[mt][nt][0] * RESCALE;
            Ls[r_ * LPAD + c_ + 1]       = acc[mt][nt][1] * RESCALE;
            Ls[(r_ + 8) * LPAD + c_]     = acc[mt][nt][2] * RESCALE;
            Ls[(r_ + 8) * LPAD + c_ + 1] = acc[mt][nt][3] * RESCALE;
        }
    }
    __syncthreads();

    // per-token max & exp-sum
    if (tid < BM) {
        const float* r = Ls + tid * LPAD;
        float m = r[0];
        #pragma unroll 4
        for (int e = 1; e < E_EXP; e++) m = fmaxf(m, r[e]);
        float s = 0.0f;
        #pragma unroll 4
        for (int e = 0; e < E_EXP; e++) s += __expf(r[e] - m);
        smax[tid]  = m;
        srsum[tid] = 1.0f / s;
    }
    __syncthreads();

    // softmax probs -> smem overwrite + coalesced logits write
    for (int i = tid; i < BM * E_EXP; i += NT) {
        const int t = i >> 7;
        const int e = i & 127;
        const float p = __expf(Ls[t * LPAD + e] - smax[t]) * srsum[t];
        Ls[t * LPAD + e] = p;
        out[(size_t)(row0 + t) * E_EXP + e] = p;
    }
    __syncthreads();

    // top-8 (strict > keeps lowest index on ties) + renormalize
    if (tid < BM) {
        float* r = Ls + tid * LPAD;
        float vals[TOPK];
        int   idxs[TOPK];
        float s = 0.0f;
        #pragma unroll
        for (int k = 0; k < TOPK; k++) {
            float bv = -1.0f;
            int   bi = 0;
            for (int e = 0; e < E_EXP; e++) {
                float v = r[e];
                if (v > bv) { bv = v; bi = e; }
            }
            r[bi]   = -1.0f;
            vals[k] = bv;
            idxs[k] = bi;
            s += bv;
        }
        const float rs = 1.0f / s;
        const size_t bw = (size_t)T * E_EXP + (size_t)(row0 + tid) * TOPK;
        const size_t bx = (size_t)T * E_EXP + (size_t)T * TOPK + (size_t)(row0 + tid) * TOPK;
        #pragma unroll
        for (int k = 0; k < TOPK; k++) {
            out[bw + k] = vals[k] * rs;
            out[bx + k] = (float)idxs[k];
        }
    }
}

extern "C" void kernel_launch(void* const* d_in, const int* in_sizes, int n_in,
                              void* d_out, int out_size)
{
    const float* X = (const float*)d_in[0];   // hidden_states [T, 2048]
    const float* W = (const float*)d_in[1];   // weight        [128, 2048]
    float* out = (float*)d_out;

    const int T = in_sizes[0] / D_DIM;        // 16384
    static int configured = -1;
    if (configured < 0) {
        cudaFuncSetAttribute(router_mma,
                             cudaFuncAttributeMaxDynamicSharedMemorySize, SMEM_B);
        configured = 1;
    }
    router_mma<<<T / BM, NT, SMEM_B>>>(X, W, out, T);
}